// round 4
// baseline (speedup 1.0000x reference)
#include <cuda_runtime.h>
#include <math.h>

#define NB 4
#define QN 10000

// Accumulator slots:
// 0..2  : sum dist_pg per level
// 3..5  : sum dist_gp per level
// 6..8  : sum edge sq-len per level
// 9..11 : sum |dot| (normal) per level
// 12..14: sum laplace sq per level
// 15..17: sum move sq per level (only 1,2 used)
// 18    : sum BCE terms
__device__ float g_acc[20];
__device__ int   g_idx0[3240];   // batch-0 argmin per level, offsets {0,156,774}

__device__ __forceinline__ float warpSum(float v) {
    #pragma unroll
    for (int o = 16; o > 0; o >>= 1) v += __shfl_down_sync(0xffffffffu, v, o);
    return v;
}

__global__ void init_kernel() {
    if (threadIdx.x < 20) g_acc[threadIdx.x] = 0.0f;
}

// ---------------------------------------------------------------------------
// Direction 1: for each pred point, min over all GT points (+argmin, batch 0)
// grid: (ceil(P/128), NB), block: 128
// 4 independent (best,idx) accumulators to break the fmin dependency chain.
// ---------------------------------------------------------------------------
template <int TILE>
__global__ void chamfer_pg_kernel(const float* __restrict__ pred, int P,
                                  const float* __restrict__ gt,
                                  int slot, int idx0_off) {
    __shared__ float4 sq[TILE];
    const int n = blockIdx.y;
    const int p = blockIdx.x * blockDim.x + threadIdx.x;
    const bool valid = (p < P);

    float px = 0.f, py = 0.f, pz = 0.f, x2 = 0.f;
    if (valid) {
        const float* pp = pred + ((size_t)n * P + p) * 3;
        px = pp[0]; py = pp[1]; pz = pp[2];
        x2 = px * px + py * py + pz * pz;
    }
    const float mx = -2.f * px, my = -2.f * py, mz = -2.f * pz;

    float best0 = 3.4e38f, best1 = 3.4e38f, best2 = 3.4e38f, best3 = 3.4e38f;
    int   bi0 = 0, bi1 = 0, bi2 = 0, bi3 = 0;
    const float* g = gt + (size_t)n * QN * 3;

    for (int q0 = 0; q0 < QN; q0 += TILE) {
        const int cnt = min(TILE, QN - q0);
        for (int t = threadIdx.x; t < cnt; t += blockDim.x) {
            const float qx = g[(q0 + t) * 3 + 0];
            const float qy = g[(q0 + t) * 3 + 1];
            const float qz = g[(q0 + t) * 3 + 2];
            sq[t] = make_float4(qx, qy, qz, qx * qx + qy * qy + qz * qz);
        }
        __syncthreads();
        int t = 0;
        for (; t + 4 <= cnt; t += 4) {
            const float4 q0v = sq[t + 0];
            const float4 q1v = sq[t + 1];
            const float4 q2v = sq[t + 2];
            const float4 q3v = sq[t + 3];
            const float d0 = fmaf(mx, q0v.x, fmaf(my, q0v.y, fmaf(mz, q0v.z, x2 + q0v.w)));
            const float d1 = fmaf(mx, q1v.x, fmaf(my, q1v.y, fmaf(mz, q1v.z, x2 + q1v.w)));
            const float d2 = fmaf(mx, q2v.x, fmaf(my, q2v.y, fmaf(mz, q2v.z, x2 + q2v.w)));
            const float d3 = fmaf(mx, q3v.x, fmaf(my, q3v.y, fmaf(mz, q3v.z, x2 + q3v.w)));
            if (d0 < best0) { best0 = d0; bi0 = q0 + t + 0; }
            if (d1 < best1) { best1 = d1; bi1 = q0 + t + 1; }
            if (d2 < best2) { best2 = d2; bi2 = q0 + t + 2; }
            if (d3 < best3) { best3 = d3; bi3 = q0 + t + 3; }
        }
        for (; t < cnt; t++) {
            const float4 q = sq[t];
            const float d = fmaf(mx, q.x, fmaf(my, q.y, fmaf(mz, q.z, x2 + q.w)));
            if (d < best0) { best0 = d; bi0 = q0 + t; }
        }
        __syncthreads();
    }

    // Merge the 4 accumulators; on exact ties, the smallest index wins
    // (matches jnp.argmin first-occurrence semantics).
    float best = best0; int bi = bi0;
    if (best1 < best || (best1 == best && bi1 < bi)) { best = best1; bi = bi1; }
    if (best2 < best || (best2 == best && bi2 < bi)) { best = best2; bi = bi2; }
    if (best3 < best || (best3 == best && bi3 < bi)) { best = best3; bi = bi3; }

    float contrib = valid ? best : 0.f;
    contrib = warpSum(contrib);
    if ((threadIdx.x & 31) == 0) atomicAdd(&g_acc[slot], contrib);
    if (valid && n == 0) g_idx0[idx0_off + p] = bi;
}

// ---------------------------------------------------------------------------
// Direction 2: for each GT point, min over all pred points of one level
// grid: (ceil(QN/256), NB), block: 256.  Whole level fits in shared (<=2466 pts).
// ---------------------------------------------------------------------------
template <int PMAX>
__global__ void chamfer_gp_kernel(const float* __restrict__ pred, int P,
                                  const float* __restrict__ gt, int slot) {
    __shared__ float4 sp[PMAX];
    const int n = blockIdx.y;
    const float* pr = pred + (size_t)n * P * 3;
    for (int t = threadIdx.x; t < P; t += blockDim.x) {
        const float x = pr[t * 3 + 0];
        const float y = pr[t * 3 + 1];
        const float z = pr[t * 3 + 2];
        sp[t] = make_float4(x, y, z, x * x + y * y + z * z);
    }
    __syncthreads();

    const int q = blockIdx.x * blockDim.x + threadIdx.x;
    float best = 0.f;
    if (q < QN) {
        const float* gq = gt + ((size_t)n * QN + q) * 3;
        const float qx = gq[0], qy = gq[1], qz = gq[2];
        const float q2 = qx * qx + qy * qy + qz * qz;
        const float mx = -2.f * qx, my = -2.f * qy, mz = -2.f * qz;
        float b0 = 3.4e38f, b1 = 3.4e38f, b2 = 3.4e38f, b3 = 3.4e38f;
        int t = 0;
        for (; t + 4 <= P; t += 4) {
            const float4 p0 = sp[t + 0];
            const float4 p1 = sp[t + 1];
            const float4 p2 = sp[t + 2];
            const float4 p3 = sp[t + 3];
            b0 = fminf(b0, fmaf(mx, p0.x, fmaf(my, p0.y, fmaf(mz, p0.z, q2 + p0.w))));
            b1 = fminf(b1, fmaf(mx, p1.x, fmaf(my, p1.y, fmaf(mz, p1.z, q2 + p1.w))));
            b2 = fminf(b2, fmaf(mx, p2.x, fmaf(my, p2.y, fmaf(mz, p2.z, q2 + p2.w))));
            b3 = fminf(b3, fmaf(mx, p3.x, fmaf(my, p3.y, fmaf(mz, p3.z, q2 + p3.w))));
        }
        for (; t < P; t++) {
            const float4 pv = sp[t];
            b0 = fminf(b0, fmaf(mx, pv.x, fmaf(my, pv.y, fmaf(mz, pv.z, q2 + pv.w))));
        }
        best = fminf(fminf(b0, b1), fminf(b2, b3));
    }
    float s = warpSum(best);
    if ((threadIdx.x & 31) == 0) atomicAdd(&g_acc[slot], s);
}

// ---------------------------------------------------------------------------
// Edge length + normal loss (needs g_idx0 from chamfer_pg of batch 0)
// thread per (n, e)
// ---------------------------------------------------------------------------
__global__ void edge_normal_kernel(const float* __restrict__ pred, int P,
                                   const int* __restrict__ edges, int E,
                                   int idx0_off,
                                   const float* __restrict__ gtn,
                                   int slot_edge, int slot_norm) {
    const int i = blockIdx.x * blockDim.x + threadIdx.x;
    float se = 0.f, sn = 0.f;
    if (i < E * NB) {
        const int e = i % E;
        const int n = i / E;
        const int a = edges[e * 2 + 0];
        const int b = edges[e * 2 + 1];
        const float* pa = pred + ((size_t)n * P + a) * 3;
        const float* pb = pred + ((size_t)n * P + b) * 3;
        const float dx = pa[0] - pb[0];
        const float dy = pa[1] - pb[1];
        const float dz = pa[2] - pb[2];
        const float l2 = dx * dx + dy * dy + dz * dz;
        se = l2;
        const float inv_e = 1.f / fmaxf(sqrtf(l2), 1e-12f);
        const int gi = g_idx0[idx0_off + a];
        const float* nr = gtn + ((size_t)n * QN + gi) * 3;
        const float nx = nr[0], ny = nr[1], nz = nr[2];
        const float inv_n = 1.f / fmaxf(sqrtf(nx * nx + ny * ny + nz * nz), 1e-12f);
        const float dot = (dx * nx + dy * ny + dz * nz) * inv_e * inv_n;
        sn = fabsf(dot);
    }
    se = warpSum(se);
    sn = warpSum(sn);
    if ((threadIdx.x & 31) == 0) {
        atomicAdd(&g_acc[slot_edge], se);
        atomicAdd(&g_acc[slot_norm], sn);
    }
}

// ---------------------------------------------------------------------------
// Laplace + move loss. thread per (n, p)
// lap row: 8 neighbor idx (all valid: randint >= 0), self idx, cnt
// ---------------------------------------------------------------------------
__global__ void lap_move_kernel(const float* __restrict__ pred,
                                const float* __restrict__ before, int P,
                                const int* __restrict__ lap,
                                int slot_lap, int slot_move) {
    const int i = blockIdx.x * blockDim.x + threadIdx.x;
    float sl = 0.f, sm = 0.f;
    if (i < P * NB) {
        const int p = i % P;
        const int n = i / P;
        const int* lr = lap + (size_t)p * 10;
        const float invc = 1.f / (float)lr[9];
        const float* B  = before + (size_t)n * P * 3;
        const float* Pr = pred   + (size_t)n * P * 3;
        float sbx = 0.f, sby = 0.f, sbz = 0.f;
        float spx = 0.f, spy = 0.f, spz = 0.f;
        #pragma unroll
        for (int j = 0; j < 8; j++) {
            const int k = lr[j];
            sbx += B[k * 3 + 0];  sby += B[k * 3 + 1];  sbz += B[k * 3 + 2];
            spx += Pr[k * 3 + 0]; spy += Pr[k * 3 + 1]; spz += Pr[k * 3 + 2];
        }
        const float bx = B[p * 3 + 0],  by = B[p * 3 + 1],  bz = B[p * 3 + 2];
        const float px = Pr[p * 3 + 0], py = Pr[p * 3 + 1], pz = Pr[p * 3 + 2];
        const float mvx = bx - px, mvy = by - py, mvz = bz - pz;
        const float dx = mvx - (sbx - spx) * invc;
        const float dy = mvy - (sby - spy) * invc;
        const float dz = mvz - (sbz - spz) * invc;
        sl = dx * dx + dy * dy + dz * dz;
        sm = mvx * mvx + mvy * mvy + mvz * mvz;
    }
    sl = warpSum(sl);
    sm = warpSum(sm);
    if ((threadIdx.x & 31) == 0) {
        atomicAdd(&g_acc[slot_lap], sl);
        atomicAdd(&g_acc[slot_move], sm);
    }
}

// ---------------------------------------------------------------------------
// BCE image loss
// ---------------------------------------------------------------------------
__global__ void bce_kernel(const float* __restrict__ gt,
                           const float* __restrict__ r, int N, int slot) {
    const int stride = gridDim.x * blockDim.x;
    float s = 0.f;
    for (int k = blockIdx.x * blockDim.x + threadIdx.x; k < N; k += stride) {
        const float g = gt[k];
        const float rv = r[k];
        s += g * __logf(rv) + (1.f - g) * __logf(1.f - rv);
    }
    s = warpSum(s);
    if ((threadIdx.x & 31) == 0) atomicAdd(&g_acc[slot], s);
}

// ---------------------------------------------------------------------------
// Finalize: combine all sums into the scalar loss
// ---------------------------------------------------------------------------
__global__ void finalize_kernel(float* out) {
    if (threadIdx.x != 0 || blockIdx.x != 0) return;
    const float Pl[3] = {156.f, 618.f, 2466.f};
    const float El[3] = {462.f, 1848.f, 7392.f};
    const float lapc[3] = {0.2f, 1.f, 1.f};
    float chamfer = 0.f, edge = 0.f, nrm = 0.f, lap = 0.f, mov = 0.f;
    for (int i = 0; i < 3; i++) {
        chamfer += g_acc[i] / (4.f * Pl[i]) + 0.55f * (g_acc[3 + i] / (4.f * (float)QN));
        edge    += g_acc[6 + i]  / (4.f * El[i]);
        nrm     += g_acc[9 + i]  / (4.f * El[i]);
        lap     += lapc[i] * g_acc[12 + i] / (4.f * Pl[i]);
        if (i > 0) mov += lapc[i] * g_acc[15 + i] / (4.f * Pl[i]);
    }
    const float img = -g_acc[18] / (4.f * 3.f * 224.f * 224.f);
    out[0] = chamfer + 1.0f * img + 0.5f * lap + 0.1f * mov + 0.1f * edge + 0.00016f * nrm;
}

// ---------------------------------------------------------------------------
// Inputs are classified BY ELEMENT COUNT, so the binding is correct whether
// metadata.txt uses reference-signature order or setup_inputs() dict order.
// Equal-size pairs (coord/before, points/normals, images/reconst) keep their
// relative order in both orderings.
// ---------------------------------------------------------------------------
extern "C" void kernel_launch(void* const* d_in, const int* in_sizes, int n_in,
                              void* d_out, int out_size) {
    const int Pl[3] = {156, 618, 2466};
    const int El[3] = {462, 1848, 7392};
    const int off[3] = {0, 156, 774};

    const int szCoord[3] = {NB * 156 * 3, NB * 618 * 3, NB * 2466 * 3};   // 1872, 7416, 29592
    const int szEdge[3]  = {462 * 2, 1848 * 2, 7392 * 2};                 // 924, 3696, 14784
    const int szLap[3]   = {156 * 10, 618 * 10, 2466 * 10};               // 1560, 6180, 24660
    const int szGt  = NB * QN * 3;                                        // 120000
    const int szImg = NB * 3 * 224 * 224;                                 // 602112

    const float* pred[3]   = {0, 0, 0};
    const float* before[3] = {0, 0, 0};
    const int*   edges[3]  = {0, 0, 0};
    const int*   lap[3]    = {0, 0, 0};
    const float* gt_pts = 0; const float* gt_nrm = 0;
    const float* gt_img = 0; const float* reconst = 0;

    for (int i = 0; i < n_in; i++) {
        const int s = in_sizes[i];
        bool done = false;
        for (int l = 0; l < 3 && !done; l++) {
            if (s == szCoord[l]) {
                if (!pred[l]) pred[l] = (const float*)d_in[i];
                else          before[l] = (const float*)d_in[i];
                done = true;
            } else if (s == szEdge[l]) {
                edges[l] = (const int*)d_in[i]; done = true;
            } else if (s == szLap[l]) {
                lap[l] = (const int*)d_in[i]; done = true;
            }
        }
        if (done) continue;
        if (s == szGt) {
            if (!gt_pts) gt_pts = (const float*)d_in[i];
            else         gt_nrm = (const float*)d_in[i];
        } else if (s == szImg) {
            if (!gt_img) gt_img = (const float*)d_in[i];
            else         reconst = (const float*)d_in[i];
        }
    }

    float* out = (float*)d_out;

    init_kernel<<<1, 32>>>();

    // Chamfer pred->gt (also produces batch-0 argmin)
    for (int i = 0; i < 3; i++) {
        dim3 grid((Pl[i] + 127) / 128, NB);
        chamfer_pg_kernel<1024><<<grid, 128>>>(pred[i], Pl[i], gt_pts, i, off[i]);
    }
    // Chamfer gt->pred
    {
        dim3 grid((QN + 255) / 256, NB);
        chamfer_gp_kernel<156><<<grid, 256>>>(pred[0], Pl[0], gt_pts, 3);
        chamfer_gp_kernel<618><<<grid, 256>>>(pred[1], Pl[1], gt_pts, 4);
        chamfer_gp_kernel<2466><<<grid, 256>>>(pred[2], Pl[2], gt_pts, 5);
    }
    // Edge + normal (after pg kernels: needs g_idx0)
    for (int i = 0; i < 3; i++) {
        int tot = El[i] * NB;
        edge_normal_kernel<<<(tot + 255) / 256, 256>>>(pred[i], Pl[i], edges[i], El[i],
                                                       off[i], gt_nrm, 6 + i, 9 + i);
    }
    // Laplace + move
    for (int i = 0; i < 3; i++) {
        int tot = Pl[i] * NB;
        lap_move_kernel<<<(tot + 255) / 256, 256>>>(pred[i], before[i], Pl[i], lap[i],
                                                    12 + i, 15 + i);
    }
    // Image BCE
    {
        const int N = NB * 3 * 224 * 224;
        bce_kernel<<<592, 256>>>(gt_img, reconst, N, 18);
    }
    finalize_kernel<<<1, 32>>>(out);
}

// round 5
// speedup vs baseline: 4.2870x; 4.2870x over previous
#include <cuda_runtime.h>
#include <math.h>

#define NB 4
#define QN 10000

// Accumulator slots:
// 0..2 pg sums, 3..5 gp sums, 6..8 edge, 9..11 normal, 12..14 laplace,
// 15..17 move, 18 bce
__device__ float g_acc[20];
__device__ int   g_idx0[3240];                  // batch-0 argmin, level offsets {0,156,774}
__device__ unsigned int       g_pg_min32[12960]; // [lvl][n][p], bases {0,624,3096}
__device__ unsigned long long g_pg_min64[3240];  // batch-0 (key<<32)|idx, bases {0,156,774}
__device__ unsigned int       g_gp_min[120000];  // [lvl][n][q], lvl stride 40000

__device__ __forceinline__ unsigned int fkey(float f) {
    unsigned int u = __float_as_uint(f);
    return (u & 0x80000000u) ? ~u : (u | 0x80000000u);
}
__device__ __forceinline__ float funkey(unsigned int k) {
    unsigned int u = (k & 0x80000000u) ? (k ^ 0x80000000u) : ~k;
    return __uint_as_float(u);
}

__device__ __forceinline__ float warpSum(float v) {
    #pragma unroll
    for (int o = 16; o > 0; o >>= 1) v += __shfl_down_sync(0xffffffffu, v, o);
    return v;
}

// ---------------------------------------------------------------------------
__global__ void init_kernel() {
    const int i = blockIdx.x * blockDim.x + threadIdx.x;
    if (i < 20) g_acc[i] = 0.0f;
    if (i < 12960) g_pg_min32[i] = 0xFFFFFFFFu;
    if (i < 3240)  g_pg_min64[i] = 0xFFFFFFFFFFFFFFFFull;
    if (i < 120000) g_gp_min[i] = 0xFFFFFFFFu;
}

// ---------------------------------------------------------------------------
// pg: per pred point, min over GT. Fused over (level, batch, pred-chunk,
// gt-chunk). GT split into 10 chunks of 1000. 1080 blocks x 128 threads.
// Block layout per level: r = ((pc*NB)+n)*10 + gc. Level bases {0,80,280}.
// ---------------------------------------------------------------------------
__global__ void chamfer_pg_fused(const float* __restrict__ p0,
                                 const float* __restrict__ p1,
                                 const float* __restrict__ p2,
                                 const float* __restrict__ gt) {
    __shared__ float4 sq[1000];
    int bid = blockIdx.x;
    int r, P, base32, base64;
    const float* pred;
    if (bid < 80)       { r = bid;       P = 156;  pred = p0; base32 = 0;    base64 = 0;   }
    else if (bid < 280) { r = bid - 80;  P = 618;  pred = p1; base32 = 624;  base64 = 156; }
    else                { r = bid - 280; P = 2466; pred = p2; base32 = 3096; base64 = 774; }
    const int gc = r % 10; r /= 10;
    const int n  = r % NB;
    const int pc = r / NB;
    const int p  = pc * 128 + threadIdx.x;
    const bool valid = (p < P);

    float px = 0.f, py = 0.f, pz = 0.f, x2 = 0.f;
    if (valid) {
        const float* pp = pred + ((size_t)n * P + p) * 3;
        px = pp[0]; py = pp[1]; pz = pp[2];
        x2 = px * px + py * py + pz * pz;
    }
    const float mx = -2.f * px, my = -2.f * py, mz = -2.f * pz;

    const float* g = gt + ((size_t)n * QN + gc * 1000) * 3;
    for (int t = threadIdx.x; t < 1000; t += 128) {
        const float qx = g[3 * t + 0];
        const float qy = g[3 * t + 1];
        const float qz = g[3 * t + 2];
        sq[t] = make_float4(qx, qy, qz, qx * qx + qy * qy + qz * qz);
    }
    __syncthreads();

    if (!valid) return;

    if (n == 0) {
        // argmin variant
        float b0 = 3.4e38f, b1 = 3.4e38f, b2 = 3.4e38f, b3 = 3.4e38f;
        int i0 = 0, i1 = 0, i2 = 0, i3 = 0;
        for (int t = 0; t < 1000; t += 4) {
            const float4 q0 = sq[t + 0];
            const float4 q1 = sq[t + 1];
            const float4 q2 = sq[t + 2];
            const float4 q3 = sq[t + 3];
            const float d0 = fmaf(mx, q0.x, fmaf(my, q0.y, fmaf(mz, q0.z, x2 + q0.w)));
            const float d1 = fmaf(mx, q1.x, fmaf(my, q1.y, fmaf(mz, q1.z, x2 + q1.w)));
            const float d2 = fmaf(mx, q2.x, fmaf(my, q2.y, fmaf(mz, q2.z, x2 + q2.w)));
            const float d3 = fmaf(mx, q3.x, fmaf(my, q3.y, fmaf(mz, q3.z, x2 + q3.w)));
            if (d0 < b0) { b0 = d0; i0 = t + 0; }
            if (d1 < b1) { b1 = d1; i1 = t + 1; }
            if (d2 < b2) { b2 = d2; i2 = t + 2; }
            if (d3 < b3) { b3 = d3; i3 = t + 3; }
        }
        float best = b0; int bi = i0;
        if (b1 < best || (b1 == best && i1 < bi)) { best = b1; bi = i1; }
        if (b2 < best || (b2 == best && i2 < bi)) { best = b2; bi = i2; }
        if (b3 < best || (b3 == best && i3 < bi)) { best = b3; bi = i3; }
        const unsigned int key = fkey(best);
        const unsigned long long k64 =
            ((unsigned long long)key << 32) | (unsigned int)(gc * 1000 + bi);
        atomicMin(&g_pg_min64[base64 + p], k64);
        atomicMin(&g_pg_min32[base32 + p], key);   // n==0 -> n*P = 0
    } else {
        // min-only variant
        float b0 = 3.4e38f, b1 = 3.4e38f, b2 = 3.4e38f, b3 = 3.4e38f;
        for (int t = 0; t < 1000; t += 4) {
            const float4 q0 = sq[t + 0];
            const float4 q1 = sq[t + 1];
            const float4 q2 = sq[t + 2];
            const float4 q3 = sq[t + 3];
            b0 = fminf(b0, fmaf(mx, q0.x, fmaf(my, q0.y, fmaf(mz, q0.z, x2 + q0.w))));
            b1 = fminf(b1, fmaf(mx, q1.x, fmaf(my, q1.y, fmaf(mz, q1.z, x2 + q1.w))));
            b2 = fminf(b2, fmaf(mx, q2.x, fmaf(my, q2.y, fmaf(mz, q2.z, x2 + q2.w))));
            b3 = fminf(b3, fmaf(mx, q3.x, fmaf(my, q3.y, fmaf(mz, q3.z, x2 + q3.w))));
        }
        const float best = fminf(fminf(b0, b1), fminf(b2, b3));
        atomicMin(&g_pg_min32[base32 + n * P + p], fkey(best));
    }
}

// ---------------------------------------------------------------------------
// gp: per GT point, min over pred points of a level. Pred split into chunks
// <=640 (lvl2: 4 chunks of 617). 960 blocks x 256 threads.
// Block layout per level: r = ((pc*NB)+n)*40 + qc. Level bases {0,160,320}.
// ---------------------------------------------------------------------------
__global__ void chamfer_gp_fused(const float* __restrict__ p0,
                                 const float* __restrict__ p1,
                                 const float* __restrict__ p2,
                                 const float* __restrict__ gt) {
    __shared__ float4 sp[640];
    int bid = blockIdx.x;
    int r, P, lvl;
    const float* pred;
    if (bid < 160)      { r = bid;       P = 156;  pred = p0; lvl = 0; }
    else if (bid < 320) { r = bid - 160; P = 618;  pred = p1; lvl = 1; }
    else                { r = bid - 320; P = 2466; pred = p2; lvl = 2; }
    const int qc = r % 40; r /= 40;
    const int n  = r % NB;
    const int pc = r / NB;
    const int start = pc * 617;                 // pc==0 for lvl0/1
    const int cnt = min((lvl == 2) ? 617 : P, P - start);

    const float* pr = pred + ((size_t)n * P + start) * 3;
    for (int t = threadIdx.x; t < cnt; t += 256) {
        const float x = pr[3 * t + 0];
        const float y = pr[3 * t + 1];
        const float z = pr[3 * t + 2];
        sp[t] = make_float4(x, y, z, x * x + y * y + z * z);
    }
    __syncthreads();

    const int q = qc * 256 + threadIdx.x;
    if (q >= QN) return;
    const float* gq = gt + ((size_t)n * QN + q) * 3;
    const float qx = gq[0], qy = gq[1], qz = gq[2];
    const float q2 = qx * qx + qy * qy + qz * qz;
    const float mx = -2.f * qx, my = -2.f * qy, mz = -2.f * qz;
    float b0 = 3.4e38f, b1 = 3.4e38f, b2 = 3.4e38f, b3 = 3.4e38f;
    int t = 0;
    for (; t + 4 <= cnt; t += 4) {
        const float4 v0 = sp[t + 0];
        const float4 v1 = sp[t + 1];
        const float4 v2 = sp[t + 2];
        const float4 v3 = sp[t + 3];
        b0 = fminf(b0, fmaf(mx, v0.x, fmaf(my, v0.y, fmaf(mz, v0.z, q2 + v0.w))));
        b1 = fminf(b1, fmaf(mx, v1.x, fmaf(my, v1.y, fmaf(mz, v1.z, q2 + v1.w))));
        b2 = fminf(b2, fmaf(mx, v2.x, fmaf(my, v2.y, fmaf(mz, v2.z, q2 + v2.w))));
        b3 = fminf(b3, fmaf(mx, v3.x, fmaf(my, v3.y, fmaf(mz, v3.z, q2 + v3.w))));
    }
    for (; t < cnt; t++) {
        const float4 v = sp[t];
        b0 = fminf(b0, fmaf(mx, v.x, fmaf(my, v.y, fmaf(mz, v.z, q2 + v.w))));
    }
    const float best = fminf(fminf(b0, b1), fminf(b2, b3));
    atomicMin(&g_gp_min[lvl * 40000 + n * QN + q], fkey(best));
}

// ---------------------------------------------------------------------------
// Reduce scratch -> g_acc sums, extract g_idx0.
// idx < 12960           : pg min values (level by {624,3096})
// idx < 132960          : gp min values (level stride 40000)
// idx < 136200          : batch-0 argmin extraction
// ---------------------------------------------------------------------------
__global__ void reduce_kernel() {
    const int idx = blockIdx.x * blockDim.x + threadIdx.x;
    float val = 0.f;
    int slot = -1;
    if (idx < 12960) {
        slot = (idx < 624) ? 0 : (idx < 3096) ? 1 : 2;
        val = funkey(g_pg_min32[idx]);
    } else if (idx < 132960) {
        const int j = idx - 12960;
        slot = 3 + j / 40000;
        val = funkey(g_gp_min[j]);
    } else if (idx < 136200) {
        const int k = idx - 132960;
        g_idx0[k] = (int)(g_pg_min64[k] & 0xFFFFFFFFull);
    }
    const unsigned m = 0xffffffffu;
    const int s0 = __shfl_sync(m, slot, 0);
    const bool uni = __all_sync(m, slot == s0);
    if (uni) {
        const float s = warpSum(val);
        if ((threadIdx.x & 31) == 0 && s0 >= 0) atomicAdd(&g_acc[s0], s);
    } else if (slot >= 0) {
        atomicAdd(&g_acc[slot], val);
    }
}

// ---------------------------------------------------------------------------
// Edge + normal, all levels fused. Ranges: lvl0 [0,1848), lvl1 [1848,9240),
// lvl2 [9240,38808). Needs g_idx0 (runs after reduce).
// ---------------------------------------------------------------------------
__global__ void edge_normal_fused(const float* __restrict__ pr0,
                                  const float* __restrict__ pr1,
                                  const float* __restrict__ pr2,
                                  const int* __restrict__ e0,
                                  const int* __restrict__ e1,
                                  const int* __restrict__ e2,
                                  const float* __restrict__ gtn) {
    int i = blockIdx.x * blockDim.x + threadIdx.x;
    float se = 0.f, sn = 0.f;
    int lvl = -1;
    if (i < 38808) {
        int E, P, off;
        const float* pred;
        const int* edges;
        if (i < 1848)      { lvl = 0; E = 462;  P = 156;  off = 0;   pred = pr0; edges = e0; }
        else if (i < 9240) { lvl = 1; E = 1848; P = 618;  off = 156; pred = pr1; edges = e1; i -= 1848; }
        else               { lvl = 2; E = 7392; P = 2466; off = 774; pred = pr2; edges = e2; i -= 9240; }
        const int e = i % E;
        const int n = i / E;
        const int a = edges[e * 2 + 0];
        const int b = edges[e * 2 + 1];
        const float* pa = pred + ((size_t)n * P + a) * 3;
        const float* pb = pred + ((size_t)n * P + b) * 3;
        const float dx = pa[0] - pb[0];
        const float dy = pa[1] - pb[1];
        const float dz = pa[2] - pb[2];
        const float l2 = dx * dx + dy * dy + dz * dz;
        se = l2;
        const float inv_e = 1.f / fmaxf(sqrtf(l2), 1e-12f);
        const int gi = g_idx0[off + a];
        const float* nr = gtn + ((size_t)n * QN + gi) * 3;
        const float nx = nr[0], ny = nr[1], nz = nr[2];
        const float inv_n = 1.f / fmaxf(sqrtf(nx * nx + ny * ny + nz * nz), 1e-12f);
        sn = fabsf((dx * nx + dy * ny + dz * nz) * inv_e * inv_n);
    }
    const unsigned m = 0xffffffffu;
    const int s0 = __shfl_sync(m, lvl, 0);
    const bool uni = __all_sync(m, lvl == s0);
    if (uni) {
        const float a = warpSum(se);
        const float b = warpSum(sn);
        if ((threadIdx.x & 31) == 0 && s0 >= 0) {
            atomicAdd(&g_acc[6 + s0], a);
            atomicAdd(&g_acc[9 + s0], b);
        }
    } else if (lvl >= 0) {
        atomicAdd(&g_acc[6 + lvl], se);
        atomicAdd(&g_acc[9 + lvl], sn);
    }
}

// ---------------------------------------------------------------------------
// Laplace + move, all levels fused. Ranges: {624, 3096, 12960}.
// ---------------------------------------------------------------------------
__global__ void lap_move_fused(const float* __restrict__ pr0,
                               const float* __restrict__ pr1,
                               const float* __restrict__ pr2,
                               const float* __restrict__ be0,
                               const float* __restrict__ be1,
                               const float* __restrict__ be2,
                               const int* __restrict__ l0,
                               const int* __restrict__ l1,
                               const int* __restrict__ l2i) {
    int i = blockIdx.x * blockDim.x + threadIdx.x;
    float sl = 0.f, sm = 0.f;
    int lvl = -1;
    if (i < 12960) {
        int P;
        const float* pred; const float* bef; const int* lap;
        if (i < 624)       { lvl = 0; P = 156;  pred = pr0; bef = be0; lap = l0; }
        else if (i < 3096) { lvl = 1; P = 618;  pred = pr1; bef = be1; lap = l1; i -= 624; }
        else               { lvl = 2; P = 2466; pred = pr2; bef = be2; lap = l2i; i -= 3096; }
        const int p = i % P;
        const int n = i / P;
        const int* lr = lap + (size_t)p * 10;
        const float invc = 1.f / (float)lr[9];
        const float* B  = bef  + (size_t)n * P * 3;
        const float* Pr = pred + (size_t)n * P * 3;
        float sbx = 0.f, sby = 0.f, sbz = 0.f;
        float spx = 0.f, spy = 0.f, spz = 0.f;
        #pragma unroll
        for (int j = 0; j < 8; j++) {
            const int k = lr[j];
            sbx += B[k * 3 + 0];  sby += B[k * 3 + 1];  sbz += B[k * 3 + 2];
            spx += Pr[k * 3 + 0]; spy += Pr[k * 3 + 1]; spz += Pr[k * 3 + 2];
        }
        const float bx = B[p * 3 + 0],  by = B[p * 3 + 1],  bz = B[p * 3 + 2];
        const float px = Pr[p * 3 + 0], py = Pr[p * 3 + 1], pz = Pr[p * 3 + 2];
        const float mvx = bx - px, mvy = by - py, mvz = bz - pz;
        const float dx = mvx - (sbx - spx) * invc;
        const float dy = mvy - (sby - spy) * invc;
        const float dz = mvz - (sbz - spz) * invc;
        sl = dx * dx + dy * dy + dz * dz;
        sm = mvx * mvx + mvy * mvy + mvz * mvz;
    }
    const unsigned m = 0xffffffffu;
    const int s0 = __shfl_sync(m, lvl, 0);
    const bool uni = __all_sync(m, lvl == s0);
    if (uni) {
        const float a = warpSum(sl);
        const float b = warpSum(sm);
        if ((threadIdx.x & 31) == 0 && s0 >= 0) {
            atomicAdd(&g_acc[12 + s0], a);
            atomicAdd(&g_acc[15 + s0], b);
        }
    } else if (lvl >= 0) {
        atomicAdd(&g_acc[12 + lvl], sl);
        atomicAdd(&g_acc[15 + lvl], sm);
    }
}

// ---------------------------------------------------------------------------
__global__ void bce_kernel(const float* __restrict__ gt,
                           const float* __restrict__ r, int N) {
    const int stride = gridDim.x * blockDim.x;
    float s = 0.f;
    for (int k = blockIdx.x * blockDim.x + threadIdx.x; k < N; k += stride) {
        const float g = gt[k];
        const float rv = r[k];
        s += g * __logf(rv) + (1.f - g) * __logf(1.f - rv);
    }
    s = warpSum(s);
    if ((threadIdx.x & 31) == 0) atomicAdd(&g_acc[18], s);
}

// ---------------------------------------------------------------------------
__global__ void finalize_kernel(float* out) {
    if (threadIdx.x != 0 || blockIdx.x != 0) return;
    const float Pl[3] = {156.f, 618.f, 2466.f};
    const float El[3] = {462.f, 1848.f, 7392.f};
    const float lapc[3] = {0.2f, 1.f, 1.f};
    float chamfer = 0.f, edge = 0.f, nrm = 0.f, lap = 0.f, mov = 0.f;
    for (int i = 0; i < 3; i++) {
        chamfer += g_acc[i] / (4.f * Pl[i]) + 0.55f * (g_acc[3 + i] / (4.f * (float)QN));
        edge    += g_acc[6 + i]  / (4.f * El[i]);
        nrm     += g_acc[9 + i]  / (4.f * El[i]);
        lap     += lapc[i] * g_acc[12 + i] / (4.f * Pl[i]);
        if (i > 0) mov += lapc[i] * g_acc[15 + i] / (4.f * Pl[i]);
    }
    const float img = -g_acc[18] / (4.f * 3.f * 224.f * 224.f);
    out[0] = chamfer + 1.0f * img + 0.5f * lap + 0.1f * mov + 0.1f * edge + 0.00016f * nrm;
}

// ---------------------------------------------------------------------------
// Inputs classified BY ELEMENT COUNT (robust to metadata ordering).
// ---------------------------------------------------------------------------
extern "C" void kernel_launch(void* const* d_in, const int* in_sizes, int n_in,
                              void* d_out, int out_size) {
    const int szCoord[3] = {NB * 156 * 3, NB * 618 * 3, NB * 2466 * 3};
    const int szEdge[3]  = {462 * 2, 1848 * 2, 7392 * 2};
    const int szLap[3]   = {156 * 10, 618 * 10, 2466 * 10};
    const int szGt  = NB * QN * 3;
    const int szImg = NB * 3 * 224 * 224;

    const float* pred[3]   = {0, 0, 0};
    const float* before[3] = {0, 0, 0};
    const int*   edges[3]  = {0, 0, 0};
    const int*   lap[3]    = {0, 0, 0};
    const float* gt_pts = 0; const float* gt_nrm = 0;
    const float* gt_img = 0; const float* reconst = 0;

    for (int i = 0; i < n_in; i++) {
        const int s = in_sizes[i];
        bool done = false;
        for (int l = 0; l < 3 && !done; l++) {
            if (s == szCoord[l]) {
                if (!pred[l]) pred[l] = (const float*)d_in[i];
                else          before[l] = (const float*)d_in[i];
                done = true;
            } else if (s == szEdge[l]) {
                edges[l] = (const int*)d_in[i]; done = true;
            } else if (s == szLap[l]) {
                lap[l] = (const int*)d_in[i]; done = true;
            }
        }
        if (done) continue;
        if (s == szGt) {
            if (!gt_pts) gt_pts = (const float*)d_in[i];
            else         gt_nrm = (const float*)d_in[i];
        } else if (s == szImg) {
            if (!gt_img) gt_img = (const float*)d_in[i];
            else         reconst = (const float*)d_in[i];
        }
    }

    float* out = (float*)d_out;

    init_kernel<<<(136200 + 255) / 256, 256>>>();
    chamfer_pg_fused<<<1080, 128>>>(pred[0], pred[1], pred[2], gt_pts);
    chamfer_gp_fused<<<960, 256>>>(pred[0], pred[1], pred[2], gt_pts);
    reduce_kernel<<<(136200 + 255) / 256, 256>>>();
    edge_normal_fused<<<(38808 + 255) / 256, 256>>>(pred[0], pred[1], pred[2],
                                                    edges[0], edges[1], edges[2], gt_nrm);
    lap_move_fused<<<(12960 + 255) / 256, 256>>>(pred[0], pred[1], pred[2],
                                                 before[0], before[1], before[2],
                                                 lap[0], lap[1], lap[2]);
    bce_kernel<<<592, 256>>>(gt_img, reconst, NB * 3 * 224 * 224);
    finalize_kernel<<<1, 32>>>(out);
}